// round 15
// baseline (speedup 1.0000x reference)
#include <cuda_runtime.h>

// ---------------------------------------------------------------------------
// CarryII R15: R12 (best, 842us) with zero blocks INTERLEAVED in launch order.
// R12 appended zero blocks after scatter blocks -> they ran concentrated at
// the kernel tail, overlapping only the last scatter wave. R13/R14 per-thread
// fusion regressed (loop + register cost in every thread). R15 keeps R12's
// one-job-per-block structure and only permutes the block->job mapping:
// block b is a zero block iff floor((b+1)*Z/T) > floor(b*Z/T), spreading the
// Z zero blocks evenly among T = S + Z blocks. Every scheduling wave then
// mixes read-heavy scatter blocks with write-only zero blocks.
// Scatter path unchanged (8 lanes/edge, 2 edges/thread, red.v4, __ldcs idx).
// ---------------------------------------------------------------------------

static constexpr int FEAT_D = 32;
static constexpr int BLK = 256;

__global__ void zero_f4_kernel(float4* __restrict__ out, long long n4) {
    long long i = blockIdx.x * (long long)blockDim.x + threadIdx.x;
    if (i < n4) out[i] = make_float4(0.f, 0.f, 0.f, 0.f);
}

__device__ __forceinline__ void red_add_v4(float* addr, float4 v) {
    asm volatile("red.global.v4.f32.add [%0], {%1, %2, %3, %4};"
                 :: "l"(addr), "f"(v.x), "f"(v.y), "f"(v.z), "f"(v.w)
                 : "memory");
}

// T = S + Z blocks: S scatter blocks for relation k, Z zero blocks for
// relation k+1's output, proportionally interleaved by block index.
__global__ void scatter_zero_kernel(const float4* __restrict__ feat,
                                    const int* __restrict__ s_idx,
                                    const int* __restrict__ d_idx,
                                    float* __restrict__ out,
                                    int n_edges, int nh,
                                    float4* __restrict__ zptr,
                                    long long zn4,
                                    int Z, int T) {
    int b = blockIdx.x;
    long long zb = (long long)b * Z / T;
    bool is_zero = ((long long)(b + 1) * Z / T) > zb;

    if (is_zero) {
        long long zi = zb * BLK + threadIdx.x;
        if (zi < zn4) zptr[zi] = make_float4(0.f, 0.f, 0.f, 0.f);
        return;
    }

    long long sb = b - zb;                       // scatter block index
    long long gid = sb * BLK + threadIdx.x;
    int pair = (int)(gid >> 3);
    if (pair >= nh) return;
    int sub = (int)(gid & 7);

    int e0 = pair;
    int e1 = pair + nh;
    bool has1 = (e1 < n_edges);

    int s0 = __ldcs(s_idx + e0);
    int d0 = __ldcs(d_idx + e0);
    int s1 = has1 ? __ldcs(s_idx + e1) : 0;
    int d1 = has1 ? __ldcs(d_idx + e1) : 0;

    float4 v0 = __ldg(feat + (long long)s0 * 8 + sub);
    float4 v1 = has1 ? __ldg(feat + (long long)s1 * 8 + sub)
                     : make_float4(0.f, 0.f, 0.f, 0.f);

    red_add_v4(out + (long long)d0 * FEAT_D + sub * 4, v0);
    if (has1) red_add_v4(out + (long long)d1 * FEAT_D + sub * 4, v1);
}

extern "C" void kernel_launch(void* const* d_in, const int* in_sizes, int n_in,
                              void* d_out, int out_size) {
    const float* u2 = (const float*)d_in[0];
    const float* u3 = (const float*)d_in[1];

    const int* S[7] = {(const int*)d_in[2], (const int*)d_in[4],
                       (const int*)d_in[6], (const int*)d_in[8],
                       (const int*)d_in[10], (const int*)d_in[12],
                       (const int*)d_in[14]};
    const int* D[7] = {(const int*)d_in[3], (const int*)d_in[5],
                       (const int*)d_in[7], (const int*)d_in[9],
                       (const int*)d_in[11], (const int*)d_in[13],
                       (const int*)d_in[15]};

    const int N3 = in_sizes[2];
    const int N4 = in_sizes[6];

    int rows[7];
    const float* feat[7];
    for (int r = 0; r < 7; r++) {
        rows[r] = (r < 2) ? N3 : N4;
        feat[r] = (r < 5) ? u2 : u3;
    }

    float* out = (float*)d_out;
    float* blk[7];
    {
        float* o = out;
        for (int r = 0; r < 7; r++) {
            blk[r] = o;
            o += (long long)rows[r] * FEAT_D;
        }
    }

    // standalone zero of block 0
    {
        long long n4 = (long long)rows[0] * 8;
        zero_f4_kernel<<<(int)((n4 + BLK - 1) / BLK), BLK>>>((float4*)blk[0], n4);
    }

    // scatter r with interleaved zero blocks for r+1
    for (int r = 0; r < 7; r++) {
        int n_edges = rows[r];
        int nh = (n_edges + 1) / 2;
        long long scat_threads = (long long)nh * 8;
        int Sb = (int)((scat_threads + BLK - 1) / BLK);

        long long zn4 = (r + 1 < 7) ? (long long)rows[r + 1] * 8 : 0;
        float4* zptr = (r + 1 < 7) ? (float4*)blk[r + 1] : nullptr;
        int Zb = (int)((zn4 + BLK - 1) / BLK);

        int T = Sb + Zb;
        scatter_zero_kernel<<<T, BLK>>>((const float4*)feat[r], S[r], D[r],
                                        blk[r], n_edges, nh, zptr, zn4, Zb, T);
    }
}

// round 16
// speedup vs baseline: 1.1008x; 1.1008x over previous
#include <cuda_runtime.h>

// ---------------------------------------------------------------------------
// CarryII R16: R15's interleaved block mapping, with the job-map computed
// ONCE PER BLOCK (thread 0 + shared broadcast) instead of per thread.
// R15's regression was pure ALU: two 64-bit divisions in every thread
// (issue 50.6%, fma 25%, alu 35%). The scheduling idea was never tested.
// Mapping: block b is a zero block iff floor((b+1)*Z/T) > floor(b*Z/T),
// spreading Z zero blocks (next relation's output) evenly among T blocks.
// Scatter path unchanged from R12/R6 (8 lanes/edge, 2 edges/thread, red.v4).
// ---------------------------------------------------------------------------

static constexpr int FEAT_D = 32;
static constexpr int BLK = 256;

__global__ void zero_f4_kernel(float4* __restrict__ out, long long n4) {
    long long i = blockIdx.x * (long long)blockDim.x + threadIdx.x;
    if (i < n4) out[i] = make_float4(0.f, 0.f, 0.f, 0.f);
}

__device__ __forceinline__ void red_add_v4(float* addr, float4 v) {
    asm volatile("red.global.v4.f32.add [%0], {%1, %2, %3, %4};"
                 :: "l"(addr), "f"(v.x), "f"(v.y), "f"(v.z), "f"(v.w)
                 : "memory");
}

__global__ void scatter_zero_kernel(const float4* __restrict__ feat,
                                    const int* __restrict__ s_idx,
                                    const int* __restrict__ d_idx,
                                    float* __restrict__ out,
                                    int n_edges, int nh,
                                    float4* __restrict__ zptr,
                                    long long zn4,
                                    int Z, int T) {
    __shared__ int s_zb, s_isz;
    if (threadIdx.x == 0) {
        long long zb0 = (long long)blockIdx.x * Z / T;       // once per block
        long long zb1 = ((long long)blockIdx.x + 1) * Z / T;
        s_zb  = (int)zb0;
        s_isz = (int)(zb1 > zb0);
    }
    __syncthreads();
    int zb = s_zb;

    if (s_isz) {
        long long zi = (long long)zb * BLK + threadIdx.x;
        if (zi < zn4) zptr[zi] = make_float4(0.f, 0.f, 0.f, 0.f);
        return;
    }

    long long gid = (long long)(blockIdx.x - zb) * BLK + threadIdx.x;
    int pair = (int)(gid >> 3);
    if (pair >= nh) return;
    int sub = (int)(gid & 7);

    int e0 = pair;
    int e1 = pair + nh;
    bool has1 = (e1 < n_edges);

    int s0 = __ldcs(s_idx + e0);
    int d0 = __ldcs(d_idx + e0);
    int s1 = has1 ? __ldcs(s_idx + e1) : 0;
    int d1 = has1 ? __ldcs(d_idx + e1) : 0;

    float4 v0 = __ldg(feat + (long long)s0 * 8 + sub);
    float4 v1 = has1 ? __ldg(feat + (long long)s1 * 8 + sub)
                     : make_float4(0.f, 0.f, 0.f, 0.f);

    red_add_v4(out + (long long)d0 * FEAT_D + sub * 4, v0);
    if (has1) red_add_v4(out + (long long)d1 * FEAT_D + sub * 4, v1);
}

extern "C" void kernel_launch(void* const* d_in, const int* in_sizes, int n_in,
                              void* d_out, int out_size) {
    const float* u2 = (const float*)d_in[0];
    const float* u3 = (const float*)d_in[1];

    const int* S[7] = {(const int*)d_in[2], (const int*)d_in[4],
                       (const int*)d_in[6], (const int*)d_in[8],
                       (const int*)d_in[10], (const int*)d_in[12],
                       (const int*)d_in[14]};
    const int* D[7] = {(const int*)d_in[3], (const int*)d_in[5],
                       (const int*)d_in[7], (const int*)d_in[9],
                       (const int*)d_in[11], (const int*)d_in[13],
                       (const int*)d_in[15]};

    const int N3 = in_sizes[2];
    const int N4 = in_sizes[6];

    int rows[7];
    const float* feat[7];
    for (int r = 0; r < 7; r++) {
        rows[r] = (r < 2) ? N3 : N4;
        feat[r] = (r < 5) ? u2 : u3;
    }

    float* out = (float*)d_out;
    float* blk[7];
    {
        float* o = out;
        for (int r = 0; r < 7; r++) {
            blk[r] = o;
            o += (long long)rows[r] * FEAT_D;
        }
    }

    // standalone zero of block 0
    {
        long long n4 = (long long)rows[0] * 8;
        zero_f4_kernel<<<(int)((n4 + BLK - 1) / BLK), BLK>>>((float4*)blk[0], n4);
    }

    // scatter r with interleaved zero blocks for r+1
    for (int r = 0; r < 7; r++) {
        int n_edges = rows[r];
        int nh = (n_edges + 1) / 2;
        long long scat_threads = (long long)nh * 8;
        int Sb = (int)((scat_threads + BLK - 1) / BLK);

        long long zn4 = (r + 1 < 7) ? (long long)rows[r + 1] * 8 : 0;
        float4* zptr = (r + 1 < 7) ? (float4*)blk[r + 1] : nullptr;
        int Zb = (int)((zn4 + BLK - 1) / BLK);

        int T = Sb + Zb;
        scatter_zero_kernel<<<T, BLK>>>((const float4*)feat[r], S[r], D[r],
                                        blk[r], n_edges, nh, zptr, zn4, Zb, T);
    }
}

// round 17
// speedup vs baseline: 1.2271x; 1.1147x over previous
#include <cuda_runtime.h>
#include <cstdint>

// ---------------------------------------------------------------------------
// CarryII R17: R12 (best, 842us: tail-block zero fusion) + evict_last-hinted
// zero stores. Insight from R15/R16 failures: tail zeros win because the
// next block's lines are freshest in L2 at kernel end, absorbing the next
// kernel's atomic RFO reads. R17 reinforces that: zero stores carry a
// createpolicy L2::evict_last hint so zeroed lines are retained
// preferentially until the following scatter's REDs land on them.
// Scatter path unchanged (8 lanes/edge, 2 edges/thread, red.v4, __ldcs idx).
// ---------------------------------------------------------------------------

static constexpr int FEAT_D = 32;
static constexpr int BLK = 256;

__device__ __forceinline__ uint64_t evict_last_policy() {
    uint64_t policy;
    asm volatile("createpolicy.fractional.L2::evict_last.b64 %0, 1.0;"
                 : "=l"(policy));
    return policy;
}

__device__ __forceinline__ void st_hint_zero_f4(float4* p, uint64_t policy) {
    asm volatile("st.global.L2::cache_hint.v4.f32 [%0], {%1, %1, %1, %1}, %2;"
                 :: "l"(p), "f"(0.0f), "l"(policy) : "memory");
}

__global__ void zero_f4_kernel(float4* __restrict__ out, long long n4) {
    long long i = blockIdx.x * (long long)blockDim.x + threadIdx.x;
    if (i < n4) {
        uint64_t pol = evict_last_policy();
        st_hint_zero_f4(out + i, pol);
    }
}

__device__ __forceinline__ void red_add_v4(float* addr, float4 v) {
    asm volatile("red.global.v4.f32.add [%0], {%1, %2, %3, %4};"
                 :: "l"(addr), "f"(v.x), "f"(v.y), "f"(v.z), "f"(v.w)
                 : "memory");
}

// Scatter for relation k; tail blocks zero relation k+1's output block
// (with evict_last retention hint).
__global__ void scatter_zero_kernel(const float4* __restrict__ feat,
                                    const int* __restrict__ s_idx,
                                    const int* __restrict__ d_idx,
                                    float* __restrict__ out,
                                    int n_edges, int nh,
                                    float4* __restrict__ zptr,  // may be null
                                    long long zn4) {
    long long gid = blockIdx.x * (long long)blockDim.x + threadIdx.x;
    long long scat_threads = (long long)nh * 8;

    if (gid >= scat_threads) {
        long long zi = gid - scat_threads;
        if (zi < zn4) {
            uint64_t pol = evict_last_policy();
            st_hint_zero_f4(zptr + zi, pol);
        }
        return;
    }

    int pair = (int)(gid >> 3);
    int sub  = (int)(gid & 7);

    int e0 = pair;
    int e1 = pair + nh;
    bool has1 = (e1 < n_edges);

    int s0 = __ldcs(s_idx + e0);
    int d0 = __ldcs(d_idx + e0);
    int s1 = has1 ? __ldcs(s_idx + e1) : 0;
    int d1 = has1 ? __ldcs(d_idx + e1) : 0;

    float4 v0 = __ldg(feat + (long long)s0 * 8 + sub);
    float4 v1 = has1 ? __ldg(feat + (long long)s1 * 8 + sub)
                     : make_float4(0.f, 0.f, 0.f, 0.f);

    red_add_v4(out + (long long)d0 * FEAT_D + sub * 4, v0);
    if (has1) red_add_v4(out + (long long)d1 * FEAT_D + sub * 4, v1);
}

extern "C" void kernel_launch(void* const* d_in, const int* in_sizes, int n_in,
                              void* d_out, int out_size) {
    const float* u2 = (const float*)d_in[0];
    const float* u3 = (const float*)d_in[1];

    const int* S[7] = {(const int*)d_in[2], (const int*)d_in[4],
                       (const int*)d_in[6], (const int*)d_in[8],
                       (const int*)d_in[10], (const int*)d_in[12],
                       (const int*)d_in[14]};
    const int* D[7] = {(const int*)d_in[3], (const int*)d_in[5],
                       (const int*)d_in[7], (const int*)d_in[9],
                       (const int*)d_in[11], (const int*)d_in[13],
                       (const int*)d_in[15]};

    const int N3 = in_sizes[2];
    const int N4 = in_sizes[6];

    int rows[7];
    const float* feat[7];
    for (int r = 0; r < 7; r++) {
        rows[r] = (r < 2) ? N3 : N4;
        feat[r] = (r < 5) ? u2 : u3;
    }

    float* out = (float*)d_out;
    float* blk[7];
    {
        float* o = out;
        for (int r = 0; r < 7; r++) {
            blk[r] = o;
            o += (long long)rows[r] * FEAT_D;
        }
    }

    // standalone zero of block 0 (hinted)
    {
        long long n4 = (long long)rows[0] * 8;
        zero_f4_kernel<<<(int)((n4 + BLK - 1) / BLK), BLK>>>((float4*)blk[0], n4);
    }

    // scatter r, fused with hinted zero of block r+1 in tail blocks
    for (int r = 0; r < 7; r++) {
        int n_edges = rows[r];
        int nh = (n_edges + 1) / 2;
        long long scat_threads = (long long)nh * 8;
        long long zn4 = (r + 1 < 7) ? (long long)rows[r + 1] * 8 : 0;
        float4* zptr = (r + 1 < 7) ? (float4*)blk[r + 1] : nullptr;

        long long total = scat_threads + zn4;
        int grid = (int)((total + BLK - 1) / BLK);
        scatter_zero_kernel<<<grid, BLK>>>((const float4*)feat[r], S[r], D[r],
                                           blk[r], n_edges, nh, zptr, zn4);
    }
}